// round 16
// baseline (speedup 1.0000x reference)
#include <cuda_runtime.h>
#include <cuda_bf16.h>
#include <cstdint>

#define OBS_LEN 20
#define PRED_LEN 30
#define MAXN 131072
#define AG 128
#define NKT 2        // k-tiles of 16 (K=32, pure Whh·h)
#define BSTR 136     // B pair-array row stride (u32 units)
#define GSTR 136     // gates row stride (floats)

typedef unsigned long long u64;
typedef unsigned int u32;
typedef unsigned short u16;

// ---------------- helpers ----------------
__device__ __forceinline__ u64 fma2(u64 a, u64 b, u64 c) {
    u64 d;
    asm("fma.rn.f32x2 %0, %1, %2, %3;" : "=l"(d) : "l"(a), "l"(b), "l"(c));
    return d;
}
__device__ __forceinline__ u64 pack2(float lo, float hi) {
    u64 d;
    asm("mov.b64 %0, {%1, %2};" : "=l"(d) : "f"(lo), "f"(hi));
    return d;
}
__device__ __forceinline__ float2 unpack2(u64 v) {
    float2 r;
    asm("mov.b64 {%0, %1}, %2;" : "=f"(r.x), "=f"(r.y) : "l"(v));
    return r;
}
__device__ __forceinline__ float hsum2(u64 v) { float2 s = unpack2(v); return s.x + s.y; }
__device__ __forceinline__ float tanha(float x) {
    float r;
    asm("tanh.approx.f32 %0, %1;" : "=f"(r) : "f"(x));
    return r;
}
__device__ __forceinline__ float sigt(float x) { return fmaf(0.5f, tanha(0.5f * x), 0.5f); }

__device__ __forceinline__ u32 bf2pack(float v0, float v1) {
    __nv_bfloat162 p = __floats2bfloat162_rn(v0, v1);
    return *(u32 *)&p;
}
__device__ __forceinline__ u16 bf1(float v) {
    __nv_bfloat16 b = __float2bfloat16(v);
    return *(u16 *)&b;
}
__device__ __forceinline__ float bf1f(u16 b) {
    __nv_bfloat16 v = *(__nv_bfloat16 *)&b;
    return __bfloat162float(v);
}

// classic bf16 tensor-core mma (baseline PTX, sm_80+, valid on sm_103)
__device__ __forceinline__ void mma16(float &d0, float &d1, float &d2, float &d3,
                                      u32 a0, u32 a1, u32 a2, u32 a3,
                                      u32 b0, u32 b1)
{
    asm volatile(
        "mma.sync.aligned.m16n8k16.row.col.f32.bf16.bf16.f32 "
        "{%0,%1,%2,%3}, {%4,%5,%6,%7}, {%8,%9}, {%0,%1,%2,%3};"
        : "+f"(d0), "+f"(d1), "+f"(d2), "+f"(d3)
        : "r"(a0), "r"(a1), "r"(a2), "r"(a3), "r"(b0), "r"(b1));
}

// ---------------- scratch ----------------
__device__ float g_h[32 * MAXN];
__device__ float g_d[32 * MAXN];

// smem layout (float/u32 units)
#define SM_BPHI 0                        // 16*136 u32
#define SM_BPLO (16 * BSTR)              // 16*136 u32
#define SM_G    (2 * 16 * BSTR)          // 128*136 float
#define SM_OW   (SM_G + 128 * GSTR)      // 72 floats
#define SM_X    (SM_OW + 72)             // 128 float2 = 256 floats
#define SMEM_FLOATS (SM_X + 256)
#define SMEM_MMA (SMEM_FLOATS * 4)

// ================= MMA LSTM kernel (enc & dec) =================
// xg/xb: enc -> lne_g / lne_b ; dec -> dec_out_w / dec_out_b
template <int STEPS, bool IS_DEC>
__global__ void __launch_bounds__(256, 2)
k_lstm_mma(const float *__restrict__ rel,
           const float *__restrict__ wih, const float *__restrict__ whh,
           const float *__restrict__ bih, const float *__restrict__ bhh,
           const float *__restrict__ embw, const float *__restrict__ embb,
           const float *__restrict__ xg, const float *__restrict__ xb,
           float *__restrict__ out, int n)
{
    extern __shared__ float sm[];
    u32 *Bhi = (u32 *)(sm + SM_BPHI);
    u32 *Blo = (u32 *)(sm + SM_BPLO);
    float *G = sm + SM_G;
    float *ow = sm + SM_OW;
    float2 *xbuf = (float2 *)(sm + SM_X);

    const int tid = threadIdx.x;
    const int lane = tid & 31;
    const int w = tid >> 5;          // MMA: warp owns gate rows [16w, 16w+16)
    const int g = lane >> 2;
    const int t = lane & 3;
    const int base = blockIdx.x * AG;

    // activation mapping: thread -> h-dim j, agent block [16*ab, 16*ab+16)
    const int aj = tid >> 3;
    const int ab = tid & 7;
    const int a0 = ab * 16;

    // ---- A fragments (pure Whh) bf16x2 hi/lo ----
    u32 ahi[NKT][4], alo[NKT][4];
#pragma unroll
    for (int kt = 0; kt < NKT; kt++) {
#pragma unroll
        for (int half = 0; half < 2; half++) {
#pragma unroll
            for (int rsel = 0; rsel < 2; rsel++) {
                const int r = 16 * w + 8 * rsel + g;
                const int k0 = 16 * kt + 2 * t + 8 * half;
                float v0 = __ldg(&whh[r * 32 + k0]);
                float v1 = __ldg(&whh[r * 32 + k0 + 1]);
                float h0 = bf1f(bf1(v0)), h1 = bf1f(bf1(v1));
                ahi[kt][half * 2 + rsel] = bf2pack(v0, v1);
                alo[kt][half * 2 + rsel] = bf2pack(v0 - h0, v1 - h1);
            }
        }
    }

    // ---- folded input weights/biases for activation rows {aj,32+aj,64+aj,96+aj} ----
    float wx0[4], wx1[4], wbv[4];
#pragma unroll
    for (int gg = 0; gg < 4; gg++) {
        const int r = gg * 32 + aj;
        float w0 = 0.f, w1 = 0.f, b = __ldg(&bih[r]) + __ldg(&bhh[r]);
#pragma unroll
        for (int e = 0; e < 16; e++) {
            float wie = __ldg(&wih[r * 16 + e]);
            w0 = fmaf(wie, __ldg(&embw[e * 2 + 0]), w0);
            w1 = fmaf(wie, __ldg(&embw[e * 2 + 1]), w1);
            b = fmaf(wie, __ldg(&embb[e]), b);
        }
        wx0[gg] = w0; wx1[gg] = w1; wbv[gg] = b;
    }

    // ---- init B pair arrays + x staging ----
    for (int i = tid; i < 16 * BSTR; i += 256) { Bhi[i] = 0u; Blo[i] = 0u; }
    __syncthreads();

    const float2 *rel2 = (const float2 *)rel;
    float2 *out2 = (float2 *)out;

    if (tid < 128) {
        const int a = tid;
        if (IS_DEC) {
#pragma unroll
            for (int kp = 0; kp < 16; kp++) {
                float v0 = g_d[(size_t)(2 * kp) * n + base + a];
                float v1 = g_d[(size_t)(2 * kp + 1) * n + base + a];
                float h0 = bf1f(bf1(v0)), h1 = bf1f(bf1(v1));
                Bhi[kp * BSTR + a] = bf2pack(v0, v1);
                Blo[kp * BSTR + a] = bf2pack(v0 - h0, v1 - h1);
            }
            xbuf[a] = __ldg(&rel2[(size_t)(OBS_LEN - 1) * n + base + a]);
        } else {
            xbuf[a] = __ldg(&rel2[base + a]);
        }
    }
    if (IS_DEC) {
        if (tid < 64) ow[tid] = __ldg(&xg[tid]);
        if (tid < 2) ow[64 + tid] = __ldg(&xb[tid]);
    }

    float c[16];
#pragma unroll
    for (int i = 0; i < 16; i++) c[i] = 0.f;

    __syncthreads();

#pragma unroll 1
    for (int st = 0; st < STEPS; st++) {
        // ---------- MMA phase: gates_h[128][128] = Whh · h ----------
#pragma unroll 4
        for (int nt = 0; nt < 16; nt++) {
            const int col = nt * 8 + g;
            // chain A: kt=0, chain B: kt=1 (independent)
            float e0 = 0.f, e1 = 0.f, e2 = 0.f, e3 = 0.f;
            float f0 = 0.f, f1 = 0.f, f2 = 0.f, f3 = 0.f;
            {
                const int r0 = t * BSTR + col;
                const int r1 = (t + 4) * BSTR + col;
                u32 bh0 = Bhi[r0], bh1 = Bhi[r1];
                u32 bl0 = Blo[r0], bl1 = Blo[r1];
                mma16(e0, e1, e2, e3, ahi[0][0], ahi[0][1], ahi[0][2], ahi[0][3], bh0, bh1);
                mma16(e0, e1, e2, e3, alo[0][0], alo[0][1], alo[0][2], alo[0][3], bh0, bh1);
                mma16(e0, e1, e2, e3, ahi[0][0], ahi[0][1], ahi[0][2], ahi[0][3], bl0, bl1);
            }
            {
                const int r0 = (8 + t) * BSTR + col;
                const int r1 = (12 + t) * BSTR + col;
                u32 bh0 = Bhi[r0], bh1 = Bhi[r1];
                u32 bl0 = Blo[r0], bl1 = Blo[r1];
                mma16(f0, f1, f2, f3, ahi[1][0], ahi[1][1], ahi[1][2], ahi[1][3], bh0, bh1);
                mma16(f0, f1, f2, f3, alo[1][0], alo[1][1], alo[1][2], alo[1][3], bh0, bh1);
                mma16(f0, f1, f2, f3, ahi[1][0], ahi[1][1], ahi[1][2], ahi[1][3], bl0, bl1);
            }
            const int R0 = 16 * w + g, R1 = R0 + 8, cb = nt * 8 + 2 * t;
            *(float2 *)(G + R0 * GSTR + cb) = make_float2(e0 + f0, e1 + f1);
            *(float2 *)(G + R1 * GSTR + cb) = make_float2(e2 + f2, e3 + f3);
        }
        __syncthreads();

        // ---------- activation phase: dim aj, agents [a0, a0+16) ----------
#pragma unroll
        for (int h8 = 0; h8 < 2; h8++) {
            const int off = a0 + h8 * 8;
            float4 vI0 = *(const float4 *)(G + aj * GSTR + off);
            float4 vI1 = *(const float4 *)(G + aj * GSTR + off + 4);
            float4 vF0 = *(const float4 *)(G + (32 + aj) * GSTR + off);
            float4 vF1 = *(const float4 *)(G + (32 + aj) * GSTR + off + 4);
            float4 vG0 = *(const float4 *)(G + (64 + aj) * GSTR + off);
            float4 vG1 = *(const float4 *)(G + (64 + aj) * GSTR + off + 4);
            float4 vO0 = *(const float4 *)(G + (96 + aj) * GSTR + off);
            float4 vO1 = *(const float4 *)(G + (96 + aj) * GSTR + off + 4);
            float gI[8] = {vI0.x, vI0.y, vI0.z, vI0.w, vI1.x, vI1.y, vI1.z, vI1.w};
            float gF[8] = {vF0.x, vF0.y, vF0.z, vF0.w, vF1.x, vF1.y, vF1.z, vF1.w};
            float gG[8] = {vG0.x, vG0.y, vG0.z, vG0.w, vG1.x, vG1.y, vG1.z, vG1.w};
            float gO[8] = {vO0.x, vO0.y, vO0.z, vO0.w, vO1.x, vO1.y, vO1.z, vO1.w};
            float hv[8];
#pragma unroll
            for (int i = 0; i < 8; i++) {
                float2 xa = xbuf[off + i];
                float aI = fmaf(wx0[0], xa.x, fmaf(wx1[0], xa.y, gI[i] + wbv[0]));
                float aF = fmaf(wx0[1], xa.x, fmaf(wx1[1], xa.y, gF[i] + wbv[1]));
                float aG = fmaf(wx0[2], xa.x, fmaf(wx1[2], xa.y, gG[i] + wbv[2]));
                float aO = fmaf(wx0[3], xa.x, fmaf(wx1[3], xa.y, gO[i] + wbv[3]));
                const int ci = h8 * 8 + i;
                float cn = fmaf(sigt(aF), c[ci], sigt(aI) * tanha(aG));
                c[ci] = cn;
                hv[i] = sigt(aO) * tanha(cn);
            }
            // fp32 h back to G row aj (for LN / projection)
            *(float4 *)(G + aj * GSTR + off) = make_float4(hv[0], hv[1], hv[2], hv[3]);
            *(float4 *)(G + aj * GSTR + off + 4) = make_float4(hv[4], hv[5], hv[6], hv[7]);
            // bf16 hi/lo into B operand
            const int pr = aj >> 1, hf = aj & 1;
#pragma unroll
            for (int i = 0; i < 8; i++) {
                u16 hh = bf1(hv[i]);
                u16 hl = bf1(hv[i] - bf1f(hh));
                ((u16 *)&Bhi[pr * BSTR + off + i])[hf] = hh;
                ((u16 *)&Blo[pr * BSTR + off + i])[hf] = hl;
            }
        }
        __syncthreads();

        if (IS_DEC) {
            if (tid < 128) {
                const int a = tid;
                float ox = ow[64], oy = ow[65];
#pragma unroll
                for (int k = 0; k < 32; k++) {
                    float hv = G[k * GSTR + a];
                    ox = fmaf(ow[k], hv, ox);
                    oy = fmaf(ow[32 + k], hv, oy);
                }
                out2[(size_t)st * n + base + a] = make_float2(ox, oy);
                xbuf[a] = make_float2(ox, oy);
            }
            __syncthreads();
        } else {
            if (tid < 128 && st + 1 < STEPS)
                xbuf[tid] = __ldg(&rel2[(size_t)(st + 1) * n + base + tid]);
            __syncthreads();
        }
    }

    if (!IS_DEC) {
        if (tid < 128) {
            const int a = tid;
            float hv[32];
#pragma unroll
            for (int k = 0; k < 32; k++) hv[k] = G[k * GSTR + a];
            float m = 0.f;
#pragma unroll
            for (int k = 0; k < 32; k++) m += hv[k];
            m *= (1.f / 32.f);
            float var = 0.f;
#pragma unroll
            for (int k = 0; k < 32; k++) { float d = hv[k] - m; var = fmaf(d, d, var); }
            float inv = rsqrtf(var * (1.f / 32.f) + 1e-5f);
#pragma unroll
            for (int k = 0; k < 32; k++)
                g_h[(size_t)k * n + base + a] =
                    fmaf((hv[k] - m) * inv, __ldg(&xg[k]), __ldg(&xb[k]));
        }
    }
}

// ================= K2: attention + context LN + MLP (unchanged, proven) =================
struct AttnSmem {
    float wq[1024], wk[1024], wv[1024], wo[1024];
    float mlp1[4096], mlp2[1536];
    float lncg[64], lncb[64], m1b[64], m2b[24], noi[8];
    float kbuf[8][32][40];
    float vbuf[8][32][40];
};

__device__ __forceinline__ float dot32p(const float *__restrict__ row, const u64 *hp)
{
    const ulonglong2 *wr = (const ulonglong2 *)row;
    u64 acc = 0ULL;
#pragma unroll
    for (int kk = 0; kk < 8; kk++) {
        ulonglong2 w = wr[kk];
        acc = fma2(w.x, hp[2 * kk], acc);
        acc = fma2(w.y, hp[2 * kk + 1], acc);
    }
    return hsum2(acc);
}
__device__ __forceinline__ float dot64p(const float *__restrict__ row, const u64 *hp)
{
    const ulonglong2 *wr = (const ulonglong2 *)row;
    u64 acc = 0ULL;
#pragma unroll
    for (int kk = 0; kk < 16; kk++) {
        ulonglong2 w = wr[kk];
        acc = fma2(w.x, hp[2 * kk], acc);
        acc = fma2(w.y, hp[2 * kk + 1], acc);
    }
    return hsum2(acc);
}

__global__ void __launch_bounds__(256)
k_attn(const float *__restrict__ wq_g, const float *__restrict__ wk_g,
       const float *__restrict__ wv_g, const float *__restrict__ wo_g,
       const float *__restrict__ lncg, const float *__restrict__ lncb,
       const float *__restrict__ m1w, const float *__restrict__ m1b,
       const float *__restrict__ m2w, const float *__restrict__ m2b,
       const float *__restrict__ noi, int n)
{
    extern __shared__ char smem_raw[];
    AttnSmem *s = (AttnSmem *)smem_raw;
    const int tid = threadIdx.x;
#define CP(d, src, c) for (int _i = tid; _i < (c); _i += 256) (d)[_i] = (src)[_i];
    CP(s->wq, wq_g, 1024) CP(s->wk, wk_g, 1024) CP(s->wv, wv_g, 1024) CP(s->wo, wo_g, 1024)
    CP(s->mlp1, m1w, 4096) CP(s->mlp2, m2w, 1536)
    CP(s->lncg, lncg, 64) CP(s->lncb, lncb, 64)
    CP(s->m1b, m1b, 64) CP(s->m2b, m2b, 24) CP(s->noi, noi, 8)
#undef CP
    __syncthreads();

    const int agent = blockIdx.x * 256 + tid;
    if (agent >= n) return;
    const int warp = tid >> 5, lane = tid & 31;

    float hv[32];
#pragma unroll
    for (int k = 0; k < 32; k++) hv[k] = __ldg(&g_h[(size_t)k * n + agent]);
    u64 hp[16];
#pragma unroll
    for (int k = 0; k < 16; k++) hp[k] = pack2(hv[2 * k], hv[2 * k + 1]);

    float q[32];
#pragma unroll
    for (int d = 0; d < 32; d++) {
        q[d] = dot32p(s->wq + d * 32, hp);
        s->kbuf[warp][lane][d] = dot32p(s->wk + d * 32, hp);
        s->vbuf[warp][lane][d] = dot32p(s->wv + d * 32, hp);
    }
    __syncwarp();

    float att[32];
#pragma unroll
    for (int hh = 0; hh < 4; hh++) {
        u64 qp[4];
#pragma unroll
        for (int i = 0; i < 4; i++) qp[i] = pack2(q[hh * 8 + 2 * i], q[hh * 8 + 2 * i + 1]);
        float sc[32], mx = -1e30f;
#pragma unroll
        for (int jj = 0; jj < 32; jj++) {
            const ulonglong2 *kr = (const ulonglong2 *)&s->kbuf[warp][jj][hh * 8];
            ulonglong2 k01 = kr[0], k23 = kr[1];
            u64 acc = fma2(k01.x, qp[0], 0ULL);
            acc = fma2(k01.y, qp[1], acc);
            acc = fma2(k23.x, qp[2], acc);
            acc = fma2(k23.y, qp[3], acc);
            float d0 = hsum2(acc) * 0.35355339059327373f;
            sc[jj] = d0;
            mx = fmaxf(mx, d0);
        }
        float sum = 0.f;
#pragma unroll
        for (int jj = 0; jj < 32; jj++) {
            float e = __expf(sc[jj] - mx);
            sc[jj] = e;
            sum += e;
        }
        float inv = __fdividef(1.f, sum);
        u64 a0 = 0, a1 = 0, a2 = 0, a3 = 0;
#pragma unroll
        for (int jj = 0; jj < 32; jj++) {
            const ulonglong2 *vr = (const ulonglong2 *)&s->vbuf[warp][jj][hh * 8];
            ulonglong2 v01 = vr[0], v23 = vr[1];
            u64 pd = pack2(sc[jj], sc[jj]);
            a0 = fma2(v01.x, pd, a0);
            a1 = fma2(v01.y, pd, a1);
            a2 = fma2(v23.x, pd, a2);
            a3 = fma2(v23.y, pd, a3);
        }
        float2 r0 = unpack2(a0), r1 = unpack2(a1), r2 = unpack2(a2), r3 = unpack2(a3);
        att[hh * 8 + 0] = r0.x * inv; att[hh * 8 + 1] = r0.y * inv;
        att[hh * 8 + 2] = r1.x * inv; att[hh * 8 + 3] = r1.y * inv;
        att[hh * 8 + 4] = r2.x * inv; att[hh * 8 + 5] = r2.y * inv;
        att[hh * 8 + 6] = r3.x * inv; att[hh * 8 + 7] = r3.y * inv;
    }

    u64 ap[16];
#pragma unroll
    for (int k = 0; k < 16; k++) ap[k] = pack2(att[2 * k], att[2 * k + 1]);
    float ctx[64];
#pragma unroll
    for (int jj = 0; jj < 32; jj++) ctx[jj] = hv[jj];
#pragma unroll
    for (int d = 0; d < 32; d++) ctx[32 + d] = dot32p(s->wo + d * 32, ap);

    {
        float m = 0.f;
#pragma unroll
        for (int jj = 0; jj < 64; jj++) m += ctx[jj];
        m *= (1.f / 64.f);
        float v = 0.f;
#pragma unroll
        for (int jj = 0; jj < 64; jj++) { float d = ctx[jj] - m; v = fmaf(d, d, v); }
        float inv = rsqrtf(v * (1.f / 64.f) + 1e-5f);
#pragma unroll
        for (int jj = 0; jj < 64; jj++)
            ctx[jj] = fmaf((ctx[jj] - m) * inv, s->lncg[jj], s->lncb[jj]);
    }

    u64 cp[32];
#pragma unroll
    for (int k = 0; k < 32; k++) cp[k] = pack2(ctx[2 * k], ctx[2 * k + 1]);
    float y1[64];
#pragma unroll
    for (int m = 0; m < 64; m++) {
        float a = dot64p(s->mlp1 + m * 64, cp) + s->m1b[m];
        y1[m] = (a > 0.f) ? a : 0.01f * a;
    }
    u64 yp[32];
#pragma unroll
    for (int k = 0; k < 32; k++) yp[k] = pack2(y1[2 * k], y1[2 * k + 1]);
#pragma unroll
    for (int m = 0; m < 24; m++) {
        float a = dot64p(s->mlp2 + m * 64, yp) + s->m2b[m];
        a = (a > 0.f) ? a : 0.01f * a;
        g_d[(size_t)m * n + agent] = a;
    }
#pragma unroll
    for (int m = 0; m < 8; m++) g_d[(size_t)(24 + m) * n + agent] = s->noi[m];
}

// ================= launch =================
extern "C" void kernel_launch(void *const *d_in, const int *in_sizes, int n_in,
                              void *d_out, int out_size)
{
    const float *rel = (const float *)d_in[1];
    const float *noise = (const float *)d_in[3];
    const float *enc_emb_w = (const float *)d_in[4];
    const float *enc_emb_b = (const float *)d_in[5];
    const float *enc_wih = (const float *)d_in[6];
    const float *enc_whh = (const float *)d_in[7];
    const float *enc_bih = (const float *)d_in[8];
    const float *enc_bhh = (const float *)d_in[9];
    const float *lne_g = (const float *)d_in[10];
    const float *lne_b = (const float *)d_in[11];
    const float *wq = (const float *)d_in[12];
    const float *wk = (const float *)d_in[13];
    const float *wv = (const float *)d_in[14];
    const float *wo = (const float *)d_in[15];
    const float *lnc_g = (const float *)d_in[16];
    const float *lnc_b = (const float *)d_in[17];
    const float *mlp1_w = (const float *)d_in[18];
    const float *mlp1_b = (const float *)d_in[19];
    const float *mlp2_w = (const float *)d_in[20];
    const float *mlp2_b = (const float *)d_in[21];
    const float *dec_emb_w = (const float *)d_in[22];
    const float *dec_emb_b = (const float *)d_in[23];
    const float *dec_wih = (const float *)d_in[24];
    const float *dec_whh = (const float *)d_in[25];
    const float *dec_bih = (const float *)d_in[26];
    const float *dec_bhh = (const float *)d_in[27];
    const float *dec_out_w = (const float *)d_in[28];
    const float *dec_out_b = (const float *)d_in[29];

    int n = in_sizes[1] / (OBS_LEN * 2);

    static bool attr_set = false;
    if (!attr_set) {
        cudaFuncSetAttribute(k_attn, cudaFuncAttributeMaxDynamicSharedMemorySize,
                             (int)sizeof(AttnSmem));
        cudaFuncSetAttribute(k_lstm_mma<OBS_LEN, false>,
                             cudaFuncAttributeMaxDynamicSharedMemorySize, SMEM_MMA);
        cudaFuncSetAttribute(k_lstm_mma<PRED_LEN, true>,
                             cudaFuncAttributeMaxDynamicSharedMemorySize, SMEM_MMA);
        cudaFuncSetAttribute(k_lstm_mma<OBS_LEN, false>,
                             cudaFuncAttributePreferredSharedMemoryCarveout,
                             cudaSharedmemCarveoutMaxShared);
        cudaFuncSetAttribute(k_lstm_mma<PRED_LEN, true>,
                             cudaFuncAttributePreferredSharedMemoryCarveout,
                             cudaSharedmemCarveoutMaxShared);
        attr_set = true;
    }

    int gridm = n / AG;

    k_lstm_mma<OBS_LEN, false><<<gridm, 256, SMEM_MMA>>>(
        rel, enc_wih, enc_whh, enc_bih, enc_bhh,
        enc_emb_w, enc_emb_b, lne_g, lne_b, nullptr, n);
    k_attn<<<(n + 255) / 256, 256, sizeof(AttnSmem)>>>(
        wq, wk, wv, wo, lnc_g, lnc_b,
        mlp1_w, mlp1_b, mlp2_w, mlp2_b, noise, n);
    k_lstm_mma<PRED_LEN, true><<<gridm, 256, SMEM_MMA>>>(
        rel, dec_wih, dec_whh, dec_bih, dec_bhh,
        dec_emb_w, dec_emb_b, dec_out_w, dec_out_b, (float *)d_out, n);
}